// round 16
// baseline (speedup 1.0000x reference)
#include <cuda_runtime.h>
#include <cuda_fp16.h>
#include <mma.h>
#include <math.h>
#include <stdint.h>

using namespace nvcuda;

#define N_NODES 116
#define N_EDGES 1160
#define C_IN    64
#define T_IN    657
#define C_OUT   256
#define F_DIM   653
#define LDF     656
#define M_ROWS  (N_NODES * C_OUT)   // 29696
#define M_TILES 232                 // 29696/128
#define N_TILES 7                   // 7 * 96 = 672
#define BN      96
#define NPAD    672
#define LKB     672                 // fp16 row stride (padded K)
#define KT_PHASE 21                 // 672/32
#define KT_TOTAL 42

#define BK      32
#define SROW    56                  // padded smem row (fp16): 112B -> conflict-free LDSM
#define A_B     (128 * 112)         // 14336
#define B_B     (96 * 112)          // 10752
#define STAGE_B (A_B + B_B)         // 25088
#define STAGES  4
#define GEMM_SMEM (STAGES * STAGE_B)   // 100352 (epilogue 128*100*4 = 51200 fits)
#define OFF_Be  7168

// conv-as-GEMM constants (persistent over 6 t-tiles, fused im2col)
#define CK      80                  // conv K = 16 ic * 5 taps
#define CSROW   88                  // A/B smem row stride (fp16) = 176B, conflict-free
#define CSA     0                   // A tile: 128*176 = 22528
#define CSB     22528               // B tile: 64*176  = 11264
#define CXS0    33792               // xs buffer 0: 16*132*4 = 8448
#define CXS1    42240               // xs buffer 1
#define CGEMM_SMEM 50688            // epilogue Cs2 (64*132*4 = 33792) overlaps A+B

extern __shared__ __align__(128) unsigned char dyn_smem[];

// ---------------- device scratch --------------------------------------------
__device__ __align__(16) __half g_aggh[(size_t)M_ROWS * LKB];
__device__ __align__(16) __half g_hh0[(size_t)M_ROWS * LKB];
__device__ __align__(16) __half g_hh1[(size_t)M_ROWS * LKB];
__device__ __align__(16) __half g_wlh[(size_t)NPAD * LKB];
__device__ __align__(16) __half g_wrh[(size_t)NPAD * LKB];
__device__ __align__(16) __half g_cwh[(size_t)C_OUT * CSROW];
__device__ int   g_offs[N_NODES + 1];
__device__ int   g_list[N_EDGES];
__device__ float g_mean[C_OUT * LDF];
__device__ float g_fc1 [C_OUT * 128];

// ---------------- helpers -----------------------------------------------------
__device__ __forceinline__ uint32_t smem_u32(const void* p) {
    uint32_t a;
    asm("{ .reg .u64 t; cvta.to.shared.u64 t, %1; cvt.u32.u64 %0, t; }" : "=r"(a) : "l"(p));
    return a;
}
__device__ __forceinline__ void cpa16(uint32_t dst, const void* src) {
    asm volatile("cp.async.cg.shared.global [%0], [%1], 16;" :: "r"(dst), "l"(src));
}
__device__ __forceinline__ void cpa4(uint32_t dst, const void* src) {
    asm volatile("cp.async.ca.shared.global [%0], [%1], 4;" :: "r"(dst), "l"(src));
}
#define CP_COMMIT() asm volatile("cp.async.commit_group;" ::: "memory")
#define CP_WAIT2()  asm volatile("cp.async.wait_group 2;" ::: "memory")
#define CP_WAIT0()  asm volatile("cp.async.wait_group 0;" ::: "memory")

__device__ __forceinline__ uint2 pack4h(float a, float b, float c, float d) {
    uint16_t ha = __half_as_ushort(__float2half_rn(a));
    uint16_t hb = __half_as_ushort(__float2half_rn(b));
    uint16_t hc = __half_as_ushort(__float2half_rn(c));
    uint16_t hd = __half_as_ushort(__float2half_rn(d));
    uint2 r;
    r.x = (uint32_t)ha | ((uint32_t)hb << 16);
    r.y = (uint32_t)hc | ((uint32_t)hd << 16);
    return r;
}

// ---------------- CSR build (edge_index arrives as int32) ---------------------
__global__ void build_csr(const int* __restrict__ ei) {
    __shared__ int cnt[N_NODES + 1];
    __shared__ int offs[N_NODES + 1];
    int tid = threadIdx.x;
    for (int i = tid; i <= N_NODES; i += blockDim.x) cnt[i] = 0;
    __syncthreads();
    for (int e = tid; e < N_EDGES; e += blockDim.x) {
        int dst = min(max(ei[N_EDGES + e], 0), N_NODES - 1);
        atomicAdd(&cnt[dst], 1);
    }
    __syncthreads();
    if (tid == 0) {
        int s = 0;
        for (int i = 0; i < N_NODES; i++) { offs[i] = s; s += cnt[i]; }
        offs[N_NODES] = s;
    }
    __syncthreads();
    for (int i = tid; i <= N_NODES; i += blockDim.x) { g_offs[i] = offs[i]; cnt[i] = offs[i]; }
    __syncthreads();
    for (int e = tid; e < N_EDGES; e += blockDim.x) {
        int src = min(max(ei[e], 0), N_NODES - 1);
        int dst = min(max(ei[N_EDGES + e], 0), N_NODES - 1);
        int pos = atomicAdd(&cnt[dst], 1);
        if (pos >= 0 && pos < N_EDGES) g_list[pos] = src;
    }
}

// ---------------- SAGE weight convert -> fp16 [672][672] ----------------------
__global__ void cw_sage(const float* __restrict__ wl, const float* __restrict__ wr) {
    int idx = blockIdx.x * blockDim.x + threadIdx.x;
    if (idx >= NPAD * (LKB / 4)) return;
    int nrow = idx / (LKB / 4);
    int k0   = (idx % (LKB / 4)) * 4;
    size_t off = (size_t)nrow * LKB + k0;
    float a[4], b[4];
#pragma unroll
    for (int e = 0; e < 4; e++) {
        int k = k0 + e;
        a[e] = (nrow < F_DIM && k < F_DIM) ? wl[(size_t)nrow * F_DIM + k] : 0.f;
        b[e] = (nrow < F_DIM && k < F_DIM) ? wr[(size_t)nrow * F_DIM + k] : 0.f;
    }
    *(uint2*)(g_wlh + off) = pack4h(a[0], a[1], a[2], a[3]);
    *(uint2*)(g_wrh + off) = pack4h(b[0], b[1], b[2], b[3]);
}

// ---------------- conv weight convert -> fp16 [256][CSROW] --------------------
__global__ void cw_conv(const float* __restrict__ cw) {
    int idx = blockIdx.x * blockDim.x + threadIdx.x;   // 256*80
    if (idx >= C_OUT * CK) return;
    int r = idx / CK, c = idx % CK;
    g_cwh[(size_t)r * CSROW + c] = __float2half_rn(cw[idx]);
}

// ---------------- persistent conv GEMM (fused im2col, 6 t-tiles/CTA) ----------
// block (n, g). Per tile tt: C[128 t x 64 oc] = A@B^T; xs double-buffered via
// cp.async; B reloaded per tile (epilogue transpose buffer overlaps it).
__global__ void __launch_bounds__(256) conv_gemm(const float* __restrict__ x,
                                                 const float* __restrict__ cb) {
    const int tid = threadIdx.x;
    const int wid = tid >> 5;
    const int n  = blockIdx.x;
    const int g  = blockIdx.y;

    const uint32_t sbase = smem_u32(dyn_smem);
    __half* sA = (__half*)dyn_smem;
    const __half* sB = (const __half*)(dyn_smem + CSB);
    const float* xb = x + ((size_t)n * C_IN + g * 16) * T_IN;
    const __half* gB = g_cwh + (size_t)g * 64 * CSROW;

    // issue xs for tile tt into buffer boff (guarded cp.async; pad -> 0)
    auto issue_xs = [&](uint32_t boff, int tt) {
        int t0 = tt * 128;
        for (int i = tid; i < 16 * 132; i += 256) {
            int ic = i / 132, o = i % 132;
            int t = t0 + o;
            if (t < T_IN) cpa4(sbase + boff + i * 4, xb + (size_t)ic * T_IN + t);
            else          *(float*)(dyn_smem + boff + i * 4) = 0.f;
        }
        CP_COMMIT();
    };
    auto issue_B = [&]() {
        for (int i = tid; i < 640; i += 256) {
            int row = i / 10, c = i % 10;
            cpa16(sbase + CSB + row * 176 + c * 16, gB + (size_t)row * CSROW + c * 8);
        }
        CP_COMMIT();
    };

    issue_B();
    issue_xs(CXS0, 0);

    const int wm = (wid & 3) * 32;
    const int wn = (wid >> 2) * 32;

    for (int tt = 0; tt < 6; tt++) {
        uint32_t xcur = (tt & 1) ? CXS1 : CXS0;
        CP_WAIT0();                 // B + xs_cur landed
        __syncthreads();

        // build A[128][80] fp16 from xs_cur: A[row][ic*5+k] = xs[ic][row+k]
        {
            const float* xs = (const float*)(dyn_smem + xcur);
            int row = tid >> 1;
            char* dstrow = (char*)sA + row * 176;
            const float* xrow = xs + row;
            if ((tid & 1) == 0) {
#pragma unroll
                for (int cp = 0; cp < 20; cp++) {
                    const int c0 = cp * 2, c1 = c0 + 1;
                    float e0 = xrow[(c0 / 5) * 132 + (c0 % 5)];
                    float e1 = xrow[(c1 / 5) * 132 + (c1 % 5)];
                    __half2 h2 = __floats2half2_rn(e0, e1);
                    *(uint32_t*)(dstrow + cp * 4) = *(uint32_t*)&h2;
                }
            } else {
#pragma unroll
                for (int cp = 20; cp < 40; cp++) {
                    const int c0 = cp * 2, c1 = c0 + 1;
                    float e0 = xrow[(c0 / 5) * 132 + (c0 % 5)];
                    float e1 = xrow[(c1 / 5) * 132 + (c1 % 5)];
                    __half2 h2 = __floats2half2_rn(e0, e1);
                    *(uint32_t*)(dstrow + cp * 4) = *(uint32_t*)&h2;
                }
            }
        }
        // prefetch next xs while we compute
        if (tt + 1 < 6) issue_xs((tt & 1) ? CXS0 : CXS1, tt + 1);
        __syncthreads();

        wmma::fragment<wmma::accumulator, 16, 16, 16, float> acc[2][2];
#pragma unroll
        for (int i = 0; i < 2; i++)
#pragma unroll
            for (int j = 0; j < 2; j++) wmma::fill_fragment(acc[i][j], 0.f);

#pragma unroll
        for (int ks = 0; ks < 5; ks++) {
            wmma::fragment<wmma::matrix_a, 16, 16, 16, __half, wmma::row_major> af[2];
            wmma::fragment<wmma::matrix_b, 16, 16, 16, __half, wmma::col_major> bf[2];
#pragma unroll
            for (int i = 0; i < 2; i++)
                wmma::load_matrix_sync(af[i], sA + (wm + i * 16) * CSROW + ks * 16, CSROW);
#pragma unroll
            for (int j = 0; j < 2; j++)
                wmma::load_matrix_sync(bf[j], sB + (wn + j * 16) * CSROW + ks * 16, CSROW);
#pragma unroll
            for (int i = 0; i < 2; i++)
#pragma unroll
                for (int j = 0; j < 2; j++)
                    wmma::mma_sync(acc[i][j], af[i], bf[j], acc[i][j]);
        }

        // epilogue: transpose through smem (clobbers sA+sB), write hh0
        __syncthreads();
        float* Cs2 = (float*)dyn_smem;
#pragma unroll
        for (int i = 0; i < 2; i++)
#pragma unroll
            for (int j = 0; j < 2; j++)
                wmma::store_matrix_sync(Cs2 + (wm + i * 16) + (size_t)(wn + j * 16) * 132,
                                        acc[i][j], 132, wmma::mem_col_major);
        __syncthreads();

        const int lane = tid & 31;
#pragma unroll
        for (int it = 0; it < 8; it++) {
            int oc = (tid >> 5) + it * 8;
            int tg = tt * 128 + lane * 4;
            if (tg < NPAD) {
                float4 v = *(float4*)&Cs2[oc * 132 + lane * 4];
                float bias = cb[g * 64 + oc];
                float v0 = (tg + 0 < F_DIM) ? v.x + bias : 0.f;
                float v1 = (tg + 1 < F_DIM) ? v.y + bias : 0.f;
                float v2 = (tg + 2 < F_DIM) ? v.z + bias : 0.f;
                float v3 = (tg + 3 < F_DIM) ? v.w + bias : 0.f;
                *(uint2*)(g_hh0 + (size_t)(n * C_OUT + g * 64 + oc) * LKB + tg) =
                    pack4h(v0, v1, v2, v3);
            }
        }
        __syncthreads();            // Cs2 reads done before B reload overwrites
        if (tt + 1 < 6) issue_B();
    }
}

// ---------------- SAGE max-aggregation (fp16 in -> fp16 out) ------------------
__global__ void sage_agg(int src) {
    const __half* h = src ? g_hh1 : g_hh0;
    int row = blockIdx.x;          // n*256 + c
    int n = row >> 8;
    int c = row & 255;
    int beg = g_offs[n], end = g_offs[n + 1];
    size_t obase = (size_t)row * LKB;
    const __half2 NEG_INF2 = __halves2half2(__ushort_as_half(0xFC00u),
                                            __ushort_as_half(0xFC00u));
    for (int v = threadIdx.x; v < LKB / 4; v += blockDim.x) {
        int f0 = v * 4;
        uint2 outv = make_uint2(0u, 0u);
        if (end > beg) {
            __half2 m0 = NEG_INF2, m1 = NEG_INF2;
            for (int e = beg; e < end; e++) {
                int s = g_list[e];
                uint2 t = *(const uint2*)(h + ((size_t)s * C_OUT + c) * LKB + f0);
                m0 = __hmax2(m0, *(__half2*)&t.x);
                m1 = __hmax2(m1, *(__half2*)&t.y);
            }
            outv.x = *(uint32_t*)&m0;
            outv.y = *(uint32_t*)&m1;
        }
        *(uint2*)(g_aggh + obase + f0) = outv;
    }
}

// ---------------- WMMA fused SAGE GEMM ----------------------------------------
// 4-stage cp.async pipeline, ONE barrier per k-iteration (BK=32 ILP kept).
__device__ __forceinline__ void stage_copy(uint32_t sbase, int tid,
                                           const __half* pA, const __half* pB) {
#pragma unroll
    for (int t = 0; t < 4; t++) {
        int idx = tid + t * 256;
        if (idx < 512) {                    // A: 128 rows x 4 chunks
            int row = idx >> 2, c = idx & 3;
            cpa16(sbase + row * 112 + c * 16, pA + (size_t)row * LKB + c * 8);
        } else if (idx < 896) {             // B: 96 rows x 4 chunks
            int j = idx - 512;
            int row = j >> 2, c = j & 3;
            cpa16(sbase + A_B + row * 112 + c * 16, pB + (size_t)row * LKB + c * 8);
        }
    }
    CP_COMMIT();
}

__global__ void __launch_bounds__(256, 2) sage_gemm(int src,
                                                    const float* __restrict__ bias) {
    __shared__ float sbias[BN];
    const int tid = threadIdx.x;
    const int wid = tid >> 5;
    const int m0 = blockIdx.x * 128;
    const int n0 = blockIdx.y * BN;

    const __half* AArr[2] = { g_aggh, src ? g_hh1 : g_hh0 };
    const __half* BArr[2] = { g_wlh, g_wrh };
    __half* OutH = src ? g_hh0 : g_hh1;

    if (tid < BN) {
        int cg = n0 + tid;
        sbias[tid] = (cg < F_DIM) ? bias[cg] : 0.f;
    }

    const uint32_t smem_base = smem_u32(dyn_smem);

    // prologue: stages 0,1,2 (all phase 0 since KT_PHASE=21 > 2)
#pragma unroll
    for (int p = 0; p < 3; p++) {
        int k0 = p * BK;
        stage_copy(smem_base + p * STAGE_B, tid,
                   AArr[0] + (size_t)m0 * LKB + k0,
                   BArr[0] + (size_t)n0 * LKB + k0);
    }

    const int wm = (wid & 3) * 32;
    const int wn = (wid >> 2) * 48;

    wmma::fragment<wmma::accumulator, 16, 16, 16, float> acc[2][3];
#pragma unroll
    for (int i = 0; i < 2; i++)
#pragma unroll
        for (int j = 0; j < 3; j++) wmma::fill_fragment(acc[i][j], 0.f);

    int buf = 0;                    // stage kt lives in buffer kt % 4
    for (int kt = 0; kt < KT_TOTAL; kt++) {
        CP_WAIT2();                 // allow 2 outstanding -> stage kt landed
        __syncthreads();            // all warps done computing kt-1 (buffer free)
        int nk = kt + 3;
        if (nk < KT_TOTAL) {        // issue into buffer (kt+3)%4 == (kt-1)%4
            int ph = (nk >= KT_PHASE) ? 1 : 0;
            int k0 = (nk - ph * KT_PHASE) * BK;
            int nbuf = buf + 3; if (nbuf >= 4) nbuf -= 4;
            stage_copy(smem_base + nbuf * STAGE_B, tid,
                       AArr[ph] + (size_t)m0 * LKB + k0,
                       BArr[ph] + (size_t)n0 * LKB + k0);
        } else {
            CP_COMMIT();            // keep group counting consistent
        }
        const __half* sA = (const __half*)(dyn_smem + buf * STAGE_B);
        const __half* sB = sA + OFF_Be;
#pragma unroll
        for (int ks = 0; ks < 2; ks++) {
            wmma::fragment<wmma::matrix_a, 16, 16, 16, __half, wmma::row_major> af[2];
            wmma::fragment<wmma::matrix_b, 16, 16, 16, __half, wmma::col_major> bf[3];
#pragma unroll
            for (int i = 0; i < 2; i++)
                wmma::load_matrix_sync(af[i], sA + (wm + i * 16) * SROW + ks * 16, SROW);
#pragma unroll
            for (int j = 0; j < 3; j++)
                wmma::load_matrix_sync(bf[j], sB + (wn + j * 16) * SROW + ks * 16, SROW);
#pragma unroll
            for (int i = 0; i < 2; i++)
#pragma unroll
                for (int j = 0; j < 3; j++)
                    wmma::mma_sync(acc[i][j], af[i], bf[j], acc[i][j]);
        }
        buf = (buf == 3) ? 0 : buf + 1;
    }

    __syncthreads();
    float* Cs = (float*)dyn_smem;       // [128][100]
#pragma unroll
    for (int i = 0; i < 2; i++)
#pragma unroll
        for (int j = 0; j < 3; j++)
            wmma::store_matrix_sync(&Cs[(wm + i * 16) * 100 + wn + j * 16], acc[i][j],
                                    100, wmma::mem_row_major);
    __syncthreads();

#pragma unroll
    for (int t = 0; t < 12; t++) {
        int q = tid + t * 256;          // 128 x 24 quads
        int row = q / 24;
        int col = (q % 24) * 4;
        float v0 = Cs[row * 100 + col + 0] + sbias[col + 0];
        float v1 = Cs[row * 100 + col + 1] + sbias[col + 1];
        float v2 = Cs[row * 100 + col + 2] + sbias[col + 2];
        float v3 = Cs[row * 100 + col + 3] + sbias[col + 3];
        int cg = n0 + col;
        int m = m0 + row;
        *(uint2*)(OutH + (size_t)m * LKB + cg) = pack4h(v0, v1, v2, v3);
    }
}

// ---------------- mean pool (fp16 in) -> g_mean fp32 ---------------------------
__global__ void mean_pool() {
    int idx = blockIdx.x * blockDim.x + threadIdx.x;
    if (idx >= C_OUT * LDF) return;
    int c = idx / LDF, f = idx % LDF;
    float s = 0.f;
    for (int n = 0; n < N_NODES; n++)
        s += __half2float(g_hh1[((size_t)n * C_OUT + c) * LKB + f]);
    g_mean[idx] = s * (1.f / N_NODES);
}

__device__ __forceinline__ float gelu_exact(float x) {
    return 0.5f * x * (1.f + erff(x * 0.70710678118654752f));
}

// ---------------- fc1 + gelu ----------------------------------------------------
__global__ void fc1_kernel(const float* __restrict__ w, const float* __restrict__ b) {
    __shared__ float row[F_DIM];
    int c = blockIdx.x;
    int tid = threadIdx.x;
    for (int f = tid; f < F_DIM; f += blockDim.x) row[f] = g_mean[c * LDF + f];
    __syncthreads();
    int warp = tid >> 5, lane = tid & 31;
    for (int g = warp; g < 128; g += blockDim.x / 32) {
        const float* wr = w + (size_t)g * F_DIM;
        float acc = 0.f;
        for (int f = lane; f < F_DIM; f += 32) acc = fmaf(row[f], wr[f], acc);
#pragma unroll
        for (int o = 16; o; o >>= 1) acc += __shfl_xor_sync(0xffffffffu, acc, o);
        if (lane == 0) g_fc1[c * 128 + g] = gelu_exact(acc + b[g]);
    }
}

// ---------------- fc2 + gelu + fc3 + softmax ------------------------------------
__global__ void head_kernel(const float* __restrict__ f2w, const float* __restrict__ f2b,
                            const float* __restrict__ f3w, const float* __restrict__ f3b,
                            float* __restrict__ out) {
    __shared__ float r1[128];
    __shared__ float r2[32];
    __shared__ float r3[4];
    int c = blockIdx.x;
    int tid = threadIdx.x;
    for (int i = tid; i < 128; i += 32) r1[i] = g_fc1[c * 128 + i];
    __syncthreads();
    {
        float acc = f2b[tid];
        const float* wr = f2w + (size_t)tid * 128;
        for (int f = 0; f < 128; f++) acc = fmaf(r1[f], wr[f], acc);
        r2[tid] = gelu_exact(acc);
    }
    __syncthreads();
    if (tid < 4) {
        float a = f3b[tid];
        const float* wr = f3w + (size_t)tid * 32;
        for (int f = 0; f < 32; f++) a = fmaf(r2[f], wr[f], a);
        r3[tid] = a;
    }
    __syncthreads();
    if (tid == 0) {
        float mx = fmaxf(fmaxf(r3[0], r3[1]), fmaxf(r3[2], r3[3]));
        float e0 = expf(r3[0] - mx), e1 = expf(r3[1] - mx);
        float e2 = expf(r3[2] - mx), e3 = expf(r3[3] - mx);
        float inv = 1.f / (e0 + e1 + e2 + e3);
        out[c * 4 + 0] = e0 * inv;
        out[c * 4 + 1] = e1 * inv;
        out[c * 4 + 2] = e2 * inv;
        out[c * 4 + 3] = e3 * inv;
    }
}

// ---------------- launch --------------------------------------------------------
extern "C" void kernel_launch(void* const* d_in, const int* in_sizes, int n_in,
                              void* d_out, int out_size) {
    const float* x      = (const float*)d_in[0];
    const int*   ei     = (const int*)d_in[1];
    const float* conv_w = (const float*)d_in[2];
    const float* conv_b = (const float*)d_in[3];
    const float* wl     = (const float*)d_in[4];
    const float* wr     = (const float*)d_in[5];
    const float* sb     = (const float*)d_in[6];
    const float* f1w    = (const float*)d_in[7];
    const float* f1b    = (const float*)d_in[8];
    const float* f2w    = (const float*)d_in[9];
    const float* f2b    = (const float*)d_in[10];
    const float* f3w    = (const float*)d_in[11];
    const float* f3b    = (const float*)d_in[12];
    float* out = (float*)d_out;

    cudaFuncSetAttribute(sage_gemm, cudaFuncAttributeMaxDynamicSharedMemorySize, GEMM_SMEM);
    cudaFuncSetAttribute(conv_gemm, cudaFuncAttributeMaxDynamicSharedMemorySize, CGEMM_SMEM);

    build_csr<<<1, 128>>>(ei);
    cw_sage<<<(NPAD * (LKB / 4) + 255) / 256, 256>>>(wl, wr);
    cw_conv<<<(C_OUT * CK + 255) / 256, 256>>>(conv_w);
    conv_gemm<<<dim3(N_NODES, 4), 256, CGEMM_SMEM>>>(x, conv_b);

    // 3 SAGE layers (fp16 ping-pong hh0 <-> hh1); layer 2 ends in hh1.
    for (int l = 0; l < 3; l++) {
        int src = l & 1;
        sage_agg<<<M_ROWS, 128>>>(src);
        sage_gemm<<<dim3(M_TILES, N_TILES), 256, GEMM_SMEM>>>(src, sb);
    }

    mean_pool<<<(C_OUT * LDF + 255) / 256, 256>>>();
    fc1_kernel<<<256, 128>>>(f1w, f1b);
    head_kernel<<<256, 32>>>(f2w, f2b, f3w, f3b, out);
}